// round 13
// baseline (speedup 1.0000x reference)
#include <cuda_runtime.h>
#include <cuda_fp16.h>
#include <cstdint>

#define DIM    256
#define HW     1024
#define NTOT   32768
#define KCODES 1024
#define MT     128
#define GBLOCKS (NTOT / MT)              // 256
#define ZQ_ELEMS  ((size_t)NTOT * DIM)
#define CODES_OFF ZQ_ELEMS
#define LOSS_OFF  (ZQ_ELEMS + (size_t)NTOT)

// gemm smem layout (4B words) — R8 proven
#define OFF_A  0                          // 128 rows * 132 words (528B rows)
#define OFF_B  16896                      // 2 stages x 128*68
#define BSTG_W 8704
#define OFF_C  34304                      // 8704
#define OFF_ES 43008                      // 1024
#define SMEM_WORDS 44032
#define SMEM_BYTES (SMEM_WORDS * 4)       // 176128

// empirically validated window constants
#define C1W 5.2e-4f
#define C3W 0.06f

__device__ __half g_zh[(size_t)NTOT * DIM];
__device__ __half g_zl[(size_t)NTOT * DIM];
__device__ __half g_eh[(size_t)KCODES * DIM];
__device__ __half g_el[(size_t)KCODES * DIM];
__device__ float  g_en2[KCODES];
__device__ int    g_en2imax;              // static 0; atomicMax idempotent across replays
__device__ float  g_zn2p[(size_t)NTOT * 8];   // per-32d-chunk partial row norms
__device__ __half g_c16[(size_t)NTOT * KCODES];
__device__ int    g_codes[NTOT];
__device__ float  g_partials[GBLOCKS];
__device__ int    g_fcnt;                 // pair-refine list
__device__ int    g_flist[NTOT];
__device__ int2   g_cand[NTOT];
__device__ int    g_fcnt2;                // overflow list
__device__ int    g_flist2[NTOT];

__device__ __forceinline__ uint32_t smem_u32(const void* p) {
    uint32_t a;
    asm("{ .reg .u64 t; cvta.to.shared.u64 t, %1; cvt.u32.u64 %0, t; }" : "=r"(a) : "l"(p));
    return a;
}
__device__ __forceinline__ void split2(float x0, float x1, uint32_t& h2, uint32_t& l2) {
    asm("cvt.rn.f16x2.f32 %0, %1, %2;" : "=r"(h2) : "f"(x1), "f"(x0));
    float f0, f1;
    asm("{ .reg .b16 l,h; mov.b32 {l,h}, %2; cvt.f32.f16 %0, l; cvt.f32.f16 %1, h; }"
        : "=f"(f0), "=f"(f1) : "r"(h2));
    asm("cvt.rn.f16x2.f32 %0, %1, %2;" : "=r"(l2) : "f"(x1 - f1), "f"(x0 - f0));
}

#define MMA16(c, a, b0, b1)                                                   \
    asm volatile("mma.sync.aligned.m16n8k16.row.col.f32.f16.f16.f32 "         \
        "{%0,%1,%2,%3}, {%4,%5,%6,%7}, {%8,%9}, {%0,%1,%2,%3};"               \
        : "+f"((c)[0]), "+f"((c)[1]), "+f"((c)[2]), "+f"((c)[3])              \
        : "r"((a)[0]), "r"((a)[1]), "r"((a)[2]), "r"((a)[3]),                 \
          "r"(b0), "r"(b1))
#define LDSM4(r0, r1, r2, r3, addr)                                           \
    asm volatile("ldmatrix.sync.aligned.m8n8.x4.shared.b16 {%0,%1,%2,%3}, [%4];" \
        : "=r"(r0), "=r"(r1), "=r"(r2), "=r"(r3) : "r"(addr))
#define CPA16(dst, src) \
    asm volatile("cp.async.cg.shared.global [%0], [%1], 16;" :: "r"(dst), "l"(src) : "memory")
#define CP_COMMIT() asm volatile("cp.async.commit_group;" ::: "memory")
#define CP_WAIT1()  asm volatile("cp.async.wait_group 1;" ::: "memory")

// merge one (v,ix) into sorted-3 with index tie-break
#define MRG(v, ix, M1, I1, M2, I2, M3)                                         \
    if ((v) < (M1) || ((v) == (M1) && (ix) < (I1))) { (M3)=(M2); (M2)=(M1); (I2)=(I1); (M1)=(v); (I1)=(ix); } \
    else if ((v) < (M2) || ((v) == (M2) && (ix) < (I2))) { (M3)=(M2); (M2)=(v); (I2)=(ix); } \
    else if ((v) < (M3)) { (M3)=(v); }

// ---------------- prepass 1: split emb + ||e||^2 + counters ----------------
__global__ void vq_prep_e(const float* __restrict__ emb) {
    if (blockIdx.x == 0 && threadIdx.x == 0) { g_fcnt = 0; g_fcnt2 = 0; }
    int gw = (blockIdx.x * blockDim.x + threadIdx.x) >> 5, lane = threadIdx.x & 31;
    if (gw >= KCODES) return;
    const float* row = emb + (size_t)gw * DIM;
    const int d0 = lane * 8;
    float4 v0 = *reinterpret_cast<const float4*>(row + d0);
    float4 v1 = *reinterpret_cast<const float4*>(row + d0 + 4);
    uint4 h, l;
    split2(v0.x, v0.y, h.x, l.x);
    split2(v0.z, v0.w, h.y, l.y);
    split2(v1.x, v1.y, h.z, l.z);
    split2(v1.z, v1.w, h.w, l.w);
    *reinterpret_cast<uint4*>(g_eh + (size_t)gw * DIM + d0) = h;
    *reinterpret_cast<uint4*>(g_el + (size_t)gw * DIM + d0) = l;
    float s = v0.x*v0.x + v0.y*v0.y + v0.z*v0.z + v0.w*v0.w
            + v1.x*v1.x + v1.y*v1.y + v1.z*v1.z + v1.w*v1.w;
    #pragma unroll
    for (int o = 16; o; o >>= 1) s += __shfl_xor_sync(0xFFFFFFFFu, s, o);
    if (lane == 0) {
        g_en2[gw] = s;
        atomicMax(&g_en2imax, __float_as_int(s));
    }
}

// ---------------- prepass 2: transpose+split z + partial row norms ----------------
__global__ void vq_prep_z(const float* __restrict__ z) {
    __shared__ float t[32][33];
    const int bx = blockIdx.x, by = blockIdx.y, bz = blockIdx.z;
    const int tx = threadIdx.x, ty = threadIdx.y;
    const float* src = z + (size_t)bz * DIM * HW + (size_t)(by * 32) * HW + bx * 32;
    #pragma unroll
    for (int j = 0; j < 4; j++) { int rr = ty + j * 8; t[rr][tx] = src[(size_t)rr * HW + tx]; }
    __syncthreads();
    const int tid = ty * 32 + tx;
    const int lane = tid & 31;
    #pragma unroll
    for (int it = 0; it < 2; it++) {
        int slot = tid + it * 256;
        int nl = slot >> 4, p = slot & 15;
        float x0 = t[2 * p][nl], x1 = t[2 * p + 1][nl];
        uint32_t h2, l2; split2(x0, x1, h2, l2);
        size_t n = (size_t)bz * HW + bx * 32 + nl;
        reinterpret_cast<uint32_t*>(g_zh)[n * 128 + by * 16 + p] = h2;
        reinterpret_cast<uint32_t*>(g_zl)[n * 128 + by * 16 + p] = l2;
        // partial row norm over this 32-d chunk (16 lanes share nl)
        float pn = fmaf(x0, x0, x1 * x1);
        #pragma unroll
        for (int o = 1; o <= 8; o <<= 1) pn += __shfl_xor_sync(0xFFFFFFFFu, pn, o);
        if ((lane & 15) == 0) g_zn2p[n * 8 + by] = pn;
    }
}

// B chunk loader
__device__ __forceinline__ void b_cpa(int c, uint32_t dstB, int tid) {
    const int nc = c >> 1, kh = c & 1;
    const __half* src = g_eh + (size_t)(nc * 128) * DIM + kh * 128;
    #pragma unroll
    for (int q = 0; q < 8; q++) {
        int idx = tid + q * 256;
        int n = idx >> 4, j = idx & 15;
        CPA16(dstB + n * 272 + j * 16, src + (size_t)n * DIM + j * 8);
    }
}

// ---------------- gemm: C16 = fp16(en2_k - 2 * zhi . ehi^T)  [R8 proven] ----------------
__global__ __launch_bounds__(256, 1)
void vq_gemm(float* __restrict__ dummy) {
    extern __shared__ __align__(16) uint32_t sw[];
    float* es = reinterpret_cast<float*>(sw + OFF_ES);
    const int tid = threadIdx.x, wid = tid >> 5, lane = tid & 31;
    const int wm = wid & 3, wn = wid >> 2;
    const int tig = lane & 3, grp = lane >> 2;
    const int n0 = blockIdx.x * MT;

    const uint32_t sbase = smem_u32(sw);
    const uint32_t aBase = sbase;
    const uint32_t bBase = sbase + OFF_B * 4;

    #pragma unroll
    for (int q = 0; q < 16; q++) {
        int idx = tid + q * 256;
        int m = idx >> 5, j = idx & 31;
        CPA16(aBase + m * 528 + j * 16, g_zh + (size_t)(n0 + m) * DIM + j * 8);
    }
    b_cpa(0, bBase, tid);
    CP_COMMIT();
    b_cpa(1, bBase + BSTG_W * 4, tid);
    CP_COMMIT();

    for (int i = tid; i < KCODES; i += 256) es[i] = g_en2[i];

    const int mrow = wm * 32 + ((lane >> 3) & 1) * 8 + (lane & 7);
    const uint32_t aAddr = aBase + mrow * 528 + (lane >> 4) * 16;
    const int nrow = wn * 64 + ((lane >> 4) << 3) + (lane & 7);
    const uint32_t bAddr0 = bBase + nrow * 272 + ((lane >> 3) & 1) * 16;

    float acc[2][8][4];

    #pragma unroll 1
    for (int c = 0; c < 16; c++) {
        const int nc = c >> 1, st = c & 1;
        CP_WAIT1();
        __syncthreads();

        if ((c & 1) == 0) {
            #pragma unroll
            for (int mt = 0; mt < 2; mt++)
                #pragma unroll
                for (int nt = 0; nt < 8; nt++)
                    #pragma unroll
                    for (int q = 0; q < 4; q++) acc[mt][nt][q] = 0.f;
        }

        #pragma unroll
        for (int kk = 0; kk < 8; kk++) {
            const uint32_t ak = (c & 1) * 256 + kk * 32;
            uint32_t ah[2][4];
            #pragma unroll
            for (int mt = 0; mt < 2; mt++)
                LDSM4(ah[mt][0], ah[mt][1], ah[mt][2], ah[mt][3],
                      aAddr + mt * (16 * 528) + ak);
            const uint32_t bk = st * (BSTG_W * 4) + kk * 32;
            #pragma unroll
            for (int ntp = 0; ntp < 4; ntp++) {
                uint32_t bh[4];
                LDSM4(bh[0], bh[1], bh[2], bh[3], bAddr0 + bk + ntp * (16 * 272));
                #pragma unroll
                for (int hf = 0; hf < 2; hf++) {
                    const int nt = ntp * 2 + hf;
                    #pragma unroll
                    for (int mt = 0; mt < 2; mt++)
                        MMA16(acc[mt][nt], ah[mt], bh[hf * 2], bh[hf * 2 + 1]);
                }
            }
        }
        __syncthreads();

        if (c & 1) {
            #pragma unroll
            for (int mt = 0; mt < 2; mt++) {
                const int rbase = wm * 32 + mt * 16 + grp;
                #pragma unroll
                for (int nt = 0; nt < 8; nt++) {
                    const int col = wn * 64 + nt * 8 + tig * 2;
                    const float e0 = es[nc * 128 + col], e1 = es[nc * 128 + col + 1];
                    const int cw = wn * 32 + nt * 4 + tig;
                    __half2 p01 = __floats2half2_rn(fmaf(-2.f, acc[mt][nt][0], e0),
                                                    fmaf(-2.f, acc[mt][nt][1], e1));
                    __half2 p23 = __floats2half2_rn(fmaf(-2.f, acc[mt][nt][2], e0),
                                                    fmaf(-2.f, acc[mt][nt][3], e1));
                    sw[OFF_C + rbase * 68 + cw]       = *reinterpret_cast<uint32_t*>(&p01);
                    sw[OFF_C + (rbase + 8) * 68 + cw] = *reinterpret_cast<uint32_t*>(&p23);
                }
            }
            __syncthreads();
            #pragma unroll
            for (int q = 0; q < 8; q++) {
                int idx = tid + q * 256;
                int rr = idx >> 4, seg = idx & 15;
                uint4 v = *reinterpret_cast<const uint4*>(sw + OFF_C + rr * 68 + seg * 4);
                *reinterpret_cast<uint4*>(g_c16 + (size_t)(n0 + rr) * KCODES + nc * 128 + seg * 8) = v;
            }
        }

        if (c + 2 < 16) { b_cpa(c + 2, bBase + st * (BSTG_W * 4), tid); CP_COMMIT(); }
    }
}

// ---------------- select: warp per row, top-3 + per-candidate sound window ----------------
__global__ __launch_bounds__(256, 1)
void vq_select(float* __restrict__ out) {
    __shared__ float ws[KCODES];
    const int tid = threadIdx.x, lane = tid & 31, wq = tid >> 5;
    for (int i = tid; i < KCODES; i += 256) ws[i] = fmaf(C1W, g_en2[i], C3W);
    __syncthreads();

    const int r = blockIdx.x * 8 + wq;

    // zn2 from 8 partials
    float pn = (lane < 8) ? g_zn2p[(size_t)r * 8 + lane] : 0.f;
    pn += __shfl_xor_sync(0xFFFFFFFFu, pn, 1);
    pn += __shfl_xor_sync(0xFFFFFFFFu, pn, 2);
    pn += __shfl_xor_sync(0xFFFFFFFFu, pn, 4);
    const float czn = C1W * __shfl_sync(0xFFFFFFFFu, pn, 0);

    // top-3 plain scores, guarded insert
    float M1 = 3.4e38f, M2 = 3.4e38f, M3 = 3.4e38f;
    int I1 = 0, I2 = 0;
    const uint4* sp = reinterpret_cast<const uint4*>(g_c16 + (size_t)r * KCODES);
    #pragma unroll
    for (int j = 0; j < 4; j++) {
        uint4 v = sp[j * 32 + lane];
        const __half2* hh = reinterpret_cast<const __half2*>(&v);
        const int kb = j * 256 + lane * 8;
        #pragma unroll
        for (int t = 0; t < 4; t++) {
            float2 s2 = __half22float2(hh[t]);
            const int k0 = kb + t * 2;
            if (s2.x < M3) {
                if (s2.x < M1)      { M3 = M2; M2 = M1; I2 = I1; M1 = s2.x; I1 = k0; }
                else if (s2.x < M2) { M3 = M2; M2 = s2.x; I2 = k0; }
                else                { M3 = s2.x; }
            }
            if (s2.y < M3) {
                if (s2.y < M1)      { M3 = M2; M2 = M1; I2 = I1; M1 = s2.y; I1 = k0 + 1; }
                else if (s2.y < M2) { M3 = M2; M2 = s2.y; I2 = k0 + 1; }
                else                { M3 = s2.y; }
            }
        }
    }
    #pragma unroll
    for (int o = 1; o <= 16; o <<= 1) {
        float om1 = __shfl_xor_sync(0xFFFFFFFFu, M1, o);
        int   oi1 = __shfl_xor_sync(0xFFFFFFFFu, I1, o);
        float om2 = __shfl_xor_sync(0xFFFFFFFFu, M2, o);
        int   oi2 = __shfl_xor_sync(0xFFFFFFFFu, I2, o);
        float om3 = __shfl_xor_sync(0xFFFFFFFFu, M3, o);
        MRG(om1, oi1, M1, I1, M2, I2, M3)
        MRG(om2, oi2, M1, I1, M2, I2, M3)
        M3 = fminf(M3, om3);
    }

    if (lane == 0) {
        g_codes[r] = I1;
        out[CODES_OFF + r] = (float)I1;
        const float w1 = ws[I1] + czn;
        const float w2 = ws[I2] + czn;
        const float wmax = fmaf(C1W, __int_as_float(g_en2imax), C3W) + czn;
        const bool c3 = (M3 - wmax <= M1 + w1);
        const bool c2 = (M2 - w2 <= M1 + w1);
        if (c3) {
            int slot = atomicAdd(&g_fcnt2, 1);
            g_flist2[slot] = r;
        } else if (c2) {
            int slot = atomicAdd(&g_fcnt, 1);
            g_flist[slot] = r;
            g_cand[r] = make_int2(I1, I2);
        }
    }
}

// ---------------- refine A: warp per row, 2 exact fp32 dots ----------------
__global__ __launch_bounds__(256, 1)
void vq_refineA(const float* __restrict__ z, const float* __restrict__ emb,
                float* __restrict__ out) {
    const int tid = threadIdx.x, lane = tid & 31, wq = tid >> 5;
    const int gw = blockIdx.x * 8 + wq;
    const int nwarp = gridDim.x * 8;
    const int cnt = g_fcnt;
    for (int i = gw; i < cnt; i += nwarp) {
        const int r = g_flist[i];
        const int2 cd = g_cand[r];
        const int bb = r >> 10, hw = r & 1023;
        const float* zr = z + (size_t)bb * DIM * HW + hw;
        float zo[8];
        #pragma unroll
        for (int t = 0; t < 8; t++) zo[t] = __ldg(zr + (size_t)(lane * 8 + t) * HW);
        float bv = 3.4e38f; int bk = 0x7FFFFFFF;
        const int ks[2] = {cd.x, cd.y};
        #pragma unroll
        for (int c = 0; c < 2; c++) {
            const int k = ks[c];
            const float4* ep = reinterpret_cast<const float4*>(emb + (size_t)k * DIM + lane * 8);
            float4 ea = __ldg(ep), eb = __ldg(ep + 1);
            float d = zo[0]*ea.x + zo[1]*ea.y + zo[2]*ea.z + zo[3]*ea.w
                    + zo[4]*eb.x + zo[5]*eb.y + zo[6]*eb.z + zo[7]*eb.w;
            #pragma unroll
            for (int o = 16; o; o >>= 1) d += __shfl_xor_sync(0xFFFFFFFFu, d, o);
            float s = __ldg(g_en2 + k) - 2.f * d;
            if (s < bv || (s == bv && k < bk)) { bv = s; bk = k; }
        }
        if (lane == 0) { g_codes[r] = bk; out[CODES_OFF + r] = (float)bk; }
    }
}

// ---------------- refine B: block per row, full fp32 scan ----------------
__global__ __launch_bounds__(256, 1)
void vq_refineB(const float* __restrict__ z, const float* __restrict__ emb,
                float* __restrict__ out) {
    __shared__ float zs[DIM];
    __shared__ float rv[8];
    __shared__ int   rix[8];
    const int tid = threadIdx.x, lane = tid & 31, wid = tid >> 5;
    const int cnt = g_fcnt2;
    for (int i = blockIdx.x; i < cnt; i += gridDim.x) {
        const int r = g_flist2[i];
        const int bb = r >> 10, hw = r & 1023;
        zs[tid] = __ldg(z + (size_t)bb * DIM * HW + (size_t)tid * HW + hw);
        __syncthreads();
        float bv = 3.4e38f; int bk = 0x7FFFFFFF;
        #pragma unroll
        for (int j = 0; j < 4; j++) {
            const int k = tid * 4 + j;
            const float4* ep = reinterpret_cast<const float4*>(emb + (size_t)k * DIM);
            float d = 0.f;
            #pragma unroll 8
            for (int q = 0; q < 64; q++) {
                float4 e = __ldg(ep + q);
                d += zs[4*q]*e.x + zs[4*q+1]*e.y + zs[4*q+2]*e.z + zs[4*q+3]*e.w;
            }
            float s = __ldg(g_en2 + k) - 2.f * d;
            if (s < bv || (s == bv && k < bk)) { bv = s; bk = k; }
        }
        #pragma unroll
        for (int o = 16; o; o >>= 1) {
            float ov = __shfl_xor_sync(0xFFFFFFFFu, bv, o);
            int   oi = __shfl_xor_sync(0xFFFFFFFFu, bk, o);
            if (ov < bv || (ov == bv && oi < bk)) { bv = ov; bk = oi; }
        }
        if (lane == 0) { rv[wid] = bv; rix[wid] = bk; }
        __syncthreads();
        if (tid == 0) {
            float v = rv[0]; int ix = rix[0];
            #pragma unroll
            for (int w = 1; w < 8; w++)
                if (rv[w] < v || (rv[w] == v && rix[w] < ix)) { v = rv[w]; ix = rix[w]; }
            g_codes[r] = ix;
            out[CODES_OFF + r] = (float)ix;
        }
        __syncthreads();
    }
}

// ---------------- gather z_q + loss ----------------
__global__ __launch_bounds__(256, 1)
void vq_gather(const float* __restrict__ z, const float* __restrict__ emb,
               float* __restrict__ out) {
    __shared__ float red[8];
    const int tid = threadIdx.x, wid = tid >> 5, lane = tid & 31;
    const int n0 = blockIdx.x * MT;
    const int b = n0 >> 10, hw0 = n0 & (HW - 1);
    const int nl = tid & 127, half = tid >> 7;
    const int code = __ldg(g_codes + n0 + nl);
    const float4* er = reinterpret_cast<const float4*>(emb + (size_t)code * DIM);
    float* zq = out + (size_t)b * DIM * HW + hw0 + nl;
    const float* zr = z + (size_t)b * DIM * HW + hw0 + nl;
    float lsum = 0.f;
    #pragma unroll 4
    for (int d4 = half; d4 < 64; d4 += 2) {
        float4 e = __ldg(er + d4);
        const int o0 = (d4 * 4) * HW;
        float z0 = zr[o0], z1 = zr[o0 + HW], z2 = zr[o0 + 2 * HW], z3 = zr[o0 + 3 * HW];
        zq[o0] = e.x; zq[o0 + HW] = e.y; zq[o0 + 2 * HW] = e.z; zq[o0 + 3 * HW] = e.w;
        float d0 = e.x - z0, d1 = e.y - z1, d2 = e.z - z2, d3 = e.w - z3;
        lsum = fmaf(d0, d0, lsum); lsum = fmaf(d1, d1, lsum);
        lsum = fmaf(d2, d2, lsum); lsum = fmaf(d3, d3, lsum);
    }
    #pragma unroll
    for (int o = 16; o; o >>= 1) lsum += __shfl_xor_sync(0xFFFFFFFFu, lsum, o);
    if (lane == 0) red[wid] = lsum;
    __syncthreads();
    if (tid == 0) {
        float s = 0.f;
        #pragma unroll
        for (int w = 0; w < 8; w++) s += red[w];
        g_partials[blockIdx.x] = s;
    }
}

// ---------------- finalize ----------------
__global__ void vq_fin(float* __restrict__ out) {
    if (threadIdx.x == 0 && blockIdx.x == 0) {
        float s = 0.f;
        for (int i = 0; i < GBLOCKS; i++) s += g_partials[i];
        out[LOSS_OFF] = 1.25f * s / (float)ZQ_ELEMS;
    }
}

extern "C" void kernel_launch(void* const* d_in, const int* in_sizes, int n_in,
                              void* d_out, int out_size) {
    const float* z   = (const float*)d_in[0];
    const float* emb = (const float*)d_in[1];
    if (n_in >= 2 && in_sizes[0] == KCODES * DIM) { const float* t = z; z = emb; emb = t; }
    float* out = (float*)d_out;

    cudaFuncSetAttribute(vq_gemm, cudaFuncAttributeMaxDynamicSharedMemorySize, SMEM_BYTES);
    vq_prep_e<<<(KCODES * 32 + 255) / 256, 256>>>(emb);
    vq_prep_z<<<dim3(32, 8, 32), dim3(32, 8)>>>(z);
    vq_gemm<<<GBLOCKS, 256, SMEM_BYTES>>>(out);
    vq_select<<<NTOT / 8, 256>>>(out);
    vq_refineA<<<128, 256>>>(z, emb, out);
    vq_refineB<<<128, 256>>>(z, emb, out);
    vq_gather<<<GBLOCKS, 256>>>(z, emb, out);
    vq_fin<<<1, 32>>>(out);
}

// round 14
// speedup vs baseline: 1.2794x; 1.2794x over previous
#include <cuda_runtime.h>
#include <cuda_fp16.h>
#include <cstdint>

#define DIM    256
#define HW     1024
#define NTOT   32768
#define KCODES 1024
#define MT     128
#define GBLOCKS (NTOT / MT)              // 256
#define ZQ_ELEMS  ((size_t)NTOT * DIM)
#define CODES_OFF ZQ_ELEMS
#define LOSS_OFF  (ZQ_ELEMS + (size_t)NTOT)

// gemm smem layout (4B words) — R8 proven
#define OFF_A  0
#define OFF_B  16896
#define BSTG_W 8704
#define OFF_C  34304
#define OFF_ES 43008
#define SMEM_WORDS 44032
#define SMEM_BYTES (SMEM_WORDS * 4)

// empirically validated window constants
#define C1W 5.2e-4f
#define C3W 0.06f

__device__ __half g_zh[(size_t)NTOT * DIM];
__device__ __half g_zl[(size_t)NTOT * DIM];
__device__ __half g_eh[(size_t)KCODES * DIM];
__device__ __half g_el[(size_t)KCODES * DIM];
__device__ float  g_en2[KCODES];
__device__ int    g_en2imax;
__device__ float  g_zn2p[(size_t)NTOT * 8];
__device__ __half g_c16[(size_t)NTOT * KCODES];
__device__ int    g_codes[NTOT];
__device__ float  g_partials[GBLOCKS];
__device__ int    g_fcnt2;                // overflow (full-scan) list
__device__ int    g_flist2[NTOT];

__device__ __forceinline__ uint32_t smem_u32(const void* p) {
    uint32_t a;
    asm("{ .reg .u64 t; cvta.to.shared.u64 t, %1; cvt.u32.u64 %0, t; }" : "=r"(a) : "l"(p));
    return a;
}
__device__ __forceinline__ void split2(float x0, float x1, uint32_t& h2, uint32_t& l2) {
    asm("cvt.rn.f16x2.f32 %0, %1, %2;" : "=r"(h2) : "f"(x1), "f"(x0));
    float f0, f1;
    asm("{ .reg .b16 l,h; mov.b32 {l,h}, %2; cvt.f32.f16 %0, l; cvt.f32.f16 %1, h; }"
        : "=f"(f0), "=f"(f1) : "r"(h2));
    asm("cvt.rn.f16x2.f32 %0, %1, %2;" : "=r"(l2) : "f"(x1 - f1), "f"(x0 - f0));
}

#define MMA16(c, a, b0, b1)                                                   \
    asm volatile("mma.sync.aligned.m16n8k16.row.col.f32.f16.f16.f32 "         \
        "{%0,%1,%2,%3}, {%4,%5,%6,%7}, {%8,%9}, {%0,%1,%2,%3};"               \
        : "+f"((c)[0]), "+f"((c)[1]), "+f"((c)[2]), "+f"((c)[3])              \
        : "r"((a)[0]), "r"((a)[1]), "r"((a)[2]), "r"((a)[3]),                 \
          "r"(b0), "r"(b1))
#define LDSM4(r0, r1, r2, r3, addr)                                           \
    asm volatile("ldmatrix.sync.aligned.m8n8.x4.shared.b16 {%0,%1,%2,%3}, [%4];" \
        : "=r"(r0), "=r"(r1), "=r"(r2), "=r"(r3) : "r"(addr))
#define CPA16(dst, src) \
    asm volatile("cp.async.cg.shared.global [%0], [%1], 16;" :: "r"(dst), "l"(src) : "memory")
#define CP_COMMIT() asm volatile("cp.async.commit_group;" ::: "memory")
#define CP_WAIT1()  asm volatile("cp.async.wait_group 1;" ::: "memory")

#define MRG(v, ix, M1, I1, M2, I2, M3)                                         \
    if ((v) < (M1) || ((v) == (M1) && (ix) < (I1))) { (M3)=(M2); (M2)=(M1); (I2)=(I1); (M1)=(v); (I1)=(ix); } \
    else if ((v) < (M2) || ((v) == (M2) && (ix) < (I2))) { (M3)=(M2); (M2)=(v); (I2)=(ix); } \
    else if ((v) < (M3)) { (M3)=(v); }

// ---------------- prepass 1: split emb + ||e||^2 ----------------
__global__ void vq_prep_e(const float* __restrict__ emb) {
    if (blockIdx.x == 0 && threadIdx.x == 0) g_fcnt2 = 0;
    int gw = (blockIdx.x * blockDim.x + threadIdx.x) >> 5, lane = threadIdx.x & 31;
    if (gw >= KCODES) return;
    const float* row = emb + (size_t)gw * DIM;
    const int d0 = lane * 8;
    float4 v0 = *reinterpret_cast<const float4*>(row + d0);
    float4 v1 = *reinterpret_cast<const float4*>(row + d0 + 4);
    uint4 h, l;
    split2(v0.x, v0.y, h.x, l.x);
    split2(v0.z, v0.w, h.y, l.y);
    split2(v1.x, v1.y, h.z, l.z);
    split2(v1.z, v1.w, h.w, l.w);
    *reinterpret_cast<uint4*>(g_eh + (size_t)gw * DIM + d0) = h;
    *reinterpret_cast<uint4*>(g_el + (size_t)gw * DIM + d0) = l;
    float s = v0.x*v0.x + v0.y*v0.y + v0.z*v0.z + v0.w*v0.w
            + v1.x*v1.x + v1.y*v1.y + v1.z*v1.z + v1.w*v1.w;
    #pragma unroll
    for (int o = 16; o; o >>= 1) s += __shfl_xor_sync(0xFFFFFFFFu, s, o);
    if (lane == 0) {
        g_en2[gw] = s;
        atomicMax(&g_en2imax, __float_as_int(s));
    }
}

// ---------------- prepass 2: transpose+split z + partial row norms ----------------
__global__ void vq_prep_z(const float* __restrict__ z) {
    __shared__ float t[32][33];
    const int bx = blockIdx.x, by = blockIdx.y, bz = blockIdx.z;
    const int tx = threadIdx.x, ty = threadIdx.y;
    const float* src = z + (size_t)bz * DIM * HW + (size_t)(by * 32) * HW + bx * 32;
    #pragma unroll
    for (int j = 0; j < 4; j++) { int rr = ty + j * 8; t[rr][tx] = src[(size_t)rr * HW + tx]; }
    __syncthreads();
    const int tid = ty * 32 + tx;
    const int lane = tid & 31;
    #pragma unroll
    for (int it = 0; it < 2; it++) {
        int slot = tid + it * 256;
        int nl = slot >> 4, p = slot & 15;
        float x0 = t[2 * p][nl], x1 = t[2 * p + 1][nl];
        uint32_t h2, l2; split2(x0, x1, h2, l2);
        size_t n = (size_t)bz * HW + bx * 32 + nl;
        reinterpret_cast<uint32_t*>(g_zh)[n * 128 + by * 16 + p] = h2;
        reinterpret_cast<uint32_t*>(g_zl)[n * 128 + by * 16 + p] = l2;
        float pn = fmaf(x0, x0, x1 * x1);
        #pragma unroll
        for (int o = 1; o <= 8; o <<= 1) pn += __shfl_xor_sync(0xFFFFFFFFu, pn, o);
        if ((lane & 15) == 0) g_zn2p[n * 8 + by] = pn;
    }
}

// B chunk loader
__device__ __forceinline__ void b_cpa(int c, uint32_t dstB, int tid) {
    const int nc = c >> 1, kh = c & 1;
    const __half* src = g_eh + (size_t)(nc * 128) * DIM + kh * 128;
    #pragma unroll
    for (int q = 0; q < 8; q++) {
        int idx = tid + q * 256;
        int n = idx >> 4, j = idx & 15;
        CPA16(dstB + n * 272 + j * 16, src + (size_t)n * DIM + j * 8);
    }
}

// ---------------- gemm: C16 = fp16(en2_k - 2 * zhi . ehi^T)  [R8 proven] ----------------
__global__ __launch_bounds__(256, 1)
void vq_gemm(float* __restrict__ dummy) {
    extern __shared__ __align__(16) uint32_t sw[];
    float* es = reinterpret_cast<float*>(sw + OFF_ES);
    const int tid = threadIdx.x, wid = tid >> 5, lane = tid & 31;
    const int wm = wid & 3, wn = wid >> 2;
    const int tig = lane & 3, grp = lane >> 2;
    const int n0 = blockIdx.x * MT;

    const uint32_t sbase = smem_u32(sw);
    const uint32_t aBase = sbase;
    const uint32_t bBase = sbase + OFF_B * 4;

    #pragma unroll
    for (int q = 0; q < 16; q++) {
        int idx = tid + q * 256;
        int m = idx >> 5, j = idx & 31;
        CPA16(aBase + m * 528 + j * 16, g_zh + (size_t)(n0 + m) * DIM + j * 8);
    }
    b_cpa(0, bBase, tid);
    CP_COMMIT();
    b_cpa(1, bBase + BSTG_W * 4, tid);
    CP_COMMIT();

    for (int i = tid; i < KCODES; i += 256) es[i] = g_en2[i];

    const int mrow = wm * 32 + ((lane >> 3) & 1) * 8 + (lane & 7);
    const uint32_t aAddr = aBase + mrow * 528 + (lane >> 4) * 16;
    const int nrow = wn * 64 + ((lane >> 4) << 3) + (lane & 7);
    const uint32_t bAddr0 = bBase + nrow * 272 + ((lane >> 3) & 1) * 16;

    float acc[2][8][4];

    #pragma unroll 1
    for (int c = 0; c < 16; c++) {
        const int nc = c >> 1, st = c & 1;
        CP_WAIT1();
        __syncthreads();

        if ((c & 1) == 0) {
            #pragma unroll
            for (int mt = 0; mt < 2; mt++)
                #pragma unroll
                for (int nt = 0; nt < 8; nt++)
                    #pragma unroll
                    for (int q = 0; q < 4; q++) acc[mt][nt][q] = 0.f;
        }

        #pragma unroll
        for (int kk = 0; kk < 8; kk++) {
            const uint32_t ak = (c & 1) * 256 + kk * 32;
            uint32_t ah[2][4];
            #pragma unroll
            for (int mt = 0; mt < 2; mt++)
                LDSM4(ah[mt][0], ah[mt][1], ah[mt][2], ah[mt][3],
                      aAddr + mt * (16 * 528) + ak);
            const uint32_t bk = st * (BSTG_W * 4) + kk * 32;
            #pragma unroll
            for (int ntp = 0; ntp < 4; ntp++) {
                uint32_t bh[4];
                LDSM4(bh[0], bh[1], bh[2], bh[3], bAddr0 + bk + ntp * (16 * 272));
                #pragma unroll
                for (int hf = 0; hf < 2; hf++) {
                    const int nt = ntp * 2 + hf;
                    #pragma unroll
                    for (int mt = 0; mt < 2; mt++)
                        MMA16(acc[mt][nt], ah[mt], bh[hf * 2], bh[hf * 2 + 1]);
                }
            }
        }
        __syncthreads();

        if (c & 1) {
            #pragma unroll
            for (int mt = 0; mt < 2; mt++) {
                const int rbase = wm * 32 + mt * 16 + grp;
                #pragma unroll
                for (int nt = 0; nt < 8; nt++) {
                    const int col = wn * 64 + nt * 8 + tig * 2;
                    const float e0 = es[nc * 128 + col], e1 = es[nc * 128 + col + 1];
                    const int cw = wn * 32 + nt * 4 + tig;
                    __half2 p01 = __floats2half2_rn(fmaf(-2.f, acc[mt][nt][0], e0),
                                                    fmaf(-2.f, acc[mt][nt][1], e1));
                    __half2 p23 = __floats2half2_rn(fmaf(-2.f, acc[mt][nt][2], e0),
                                                    fmaf(-2.f, acc[mt][nt][3], e1));
                    sw[OFF_C + rbase * 68 + cw]       = *reinterpret_cast<uint32_t*>(&p01);
                    sw[OFF_C + (rbase + 8) * 68 + cw] = *reinterpret_cast<uint32_t*>(&p23);
                }
            }
            __syncthreads();
            #pragma unroll
            for (int q = 0; q < 8; q++) {
                int idx = tid + q * 256;
                int rr = idx >> 4, seg = idx & 15;
                uint4 v = *reinterpret_cast<const uint4*>(sw + OFF_C + rr * 68 + seg * 4);
                *reinterpret_cast<uint4*>(g_c16 + (size_t)(n0 + rr) * KCODES + nc * 128 + seg * 8) = v;
            }
        }

        if (c + 2 < 16) { b_cpa(c + 2, bBase + st * (BSTG_W * 4), tid); CP_COMMIT(); }
    }
}

// ---------------- select: pack-pruned top-3 + inline 2-candidate exact refine ----------------
__global__ __launch_bounds__(256, 1)
void vq_select(const float* __restrict__ z, const float* __restrict__ emb,
               float* __restrict__ out) {
    const int tid = threadIdx.x, lane = tid & 31, wq = tid >> 5;
    const int r = blockIdx.x * 8 + wq;

    // zn2 from 8 partials
    float pn = (lane < 8) ? g_zn2p[(size_t)r * 8 + lane] : 0.f;
    #pragma unroll
    for (int o = 1; o <= 4; o <<= 1) pn += __shfl_xor_sync(0xFFFFFFFFu, pn, o);
    const float czn = C1W * __shfl_sync(0xFFFFFFFFu, pn, 0);

    // pack-pruned per-lane top-3 (ascending k within lane)
    float M1 = 3.4e38f, M2 = 3.4e38f, M3 = 3.4e38f;
    int I1 = 0, I2 = 0;
    __half Th = __ushort_as_half((unsigned short)0x7C00u);   // +inf
    const uint4* sp = reinterpret_cast<const uint4*>(g_c16 + (size_t)r * KCODES);
    #pragma unroll
    for (int j = 0; j < 4; j++) {
        uint4 v = sp[j * 32 + lane];
        const __half2* hh = reinterpret_cast<const __half2*>(&v);
        __half2 mm = __hmin2(__hmin2(hh[0], hh[1]), __hmin2(hh[2], hh[3]));
        __half pm = __hmin(__low2half(mm), __high2half(mm));
        if (__hlt(pm, Th)) {
            const int kb = j * 256 + lane * 8;
            #pragma unroll
            for (int t = 0; t < 4; t++) {
                float2 s2 = __half22float2(hh[t]);
                const int k0 = kb + t * 2;
                if (s2.x < M3) {
                    if (s2.x < M1)      { M3 = M2; M2 = M1; I2 = I1; M1 = s2.x; I1 = k0; }
                    else if (s2.x < M2) { M3 = M2; M2 = s2.x; I2 = k0; }
                    else                { M3 = s2.x; }
                }
                if (s2.y < M3) {
                    if (s2.y < M1)      { M3 = M2; M2 = M1; I2 = I1; M1 = s2.y; I1 = k0 + 1; }
                    else if (s2.y < M2) { M3 = M2; M2 = s2.y; I2 = k0 + 1; }
                    else                { M3 = s2.y; }
                }
            }
            Th = __float2half_ru(M3);
        }
    }
    #pragma unroll
    for (int o = 1; o <= 16; o <<= 1) {
        float om1 = __shfl_xor_sync(0xFFFFFFFFu, M1, o);
        int   oi1 = __shfl_xor_sync(0xFFFFFFFFu, I1, o);
        float om2 = __shfl_xor_sync(0xFFFFFFFFu, M2, o);
        int   oi2 = __shfl_xor_sync(0xFFFFFFFFu, I2, o);
        float om3 = __shfl_xor_sync(0xFFFFFFFFu, M3, o);
        MRG(om1, oi1, M1, I1, M2, I2, M3)
        MRG(om2, oi2, M1, I1, M2, I2, M3)
        M3 = fminf(M3, om3);
    }

    // window decision (lane 0 computes, broadcast)
    int decision;   // 0 = accept I1; 1 = inline pair refine; 2 = overflow
    if (lane == 0) {
        const float w1 = fmaf(C1W, __ldg(g_en2 + I1), C3W) + czn;
        const float wmax = fmaf(C1W, __int_as_float(g_en2imax), C3W) + czn;
        if (M3 - wmax <= M1 + w1) decision = 2;
        else {
            const float w2 = fmaf(C1W, __ldg(g_en2 + I2), C3W) + czn;
            decision = (M2 - w2 <= M1 + w1) ? 1 : 0;
        }
    }
    decision = __shfl_sync(0xFFFFFFFFu, decision, 0);

    if (decision == 0) {
        if (lane == 0) { g_codes[r] = I1; out[CODES_OFF + r] = (float)I1; }
        return;
    }
    if (decision == 2) {
        if (lane == 0) {
            int slot = atomicAdd(&g_fcnt2, 1);
            g_flist2[slot] = r;
            g_codes[r] = I1;                    // provisional (refineB overwrites)
            out[CODES_OFF + r] = (float)I1;
        }
        return;
    }

    // inline exact fp32 refine over {I1, I2}
    const int i1b = __shfl_sync(0xFFFFFFFFu, I1, 0);
    const int i2b = __shfl_sync(0xFFFFFFFFu, I2, 0);
    const int bb = r >> 10, hw = r & 1023;
    const float* zr = z + (size_t)bb * DIM * HW + hw;
    float zo[8];
    #pragma unroll
    for (int t = 0; t < 8; t++) zo[t] = __ldg(zr + (size_t)(lane * 8 + t) * HW);
    float bv = 3.4e38f; int bk = 0x7FFFFFFF;
    const int ks[2] = {i1b, i2b};
    #pragma unroll
    for (int c = 0; c < 2; c++) {
        const int k = ks[c];
        const float4* ep = reinterpret_cast<const float4*>(emb + (size_t)k * DIM + lane * 8);
        float4 ea = __ldg(ep), eb = __ldg(ep + 1);
        float d = zo[0]*ea.x + zo[1]*ea.y + zo[2]*ea.z + zo[3]*ea.w
                + zo[4]*eb.x + zo[5]*eb.y + zo[6]*eb.z + zo[7]*eb.w;
        #pragma unroll
        for (int o = 16; o; o >>= 1) d += __shfl_xor_sync(0xFFFFFFFFu, d, o);
        float s = __ldg(g_en2 + k) - 2.f * d;
        if (s < bv || (s == bv && k < bk)) { bv = s; bk = k; }
    }
    if (lane == 0) { g_codes[r] = bk; out[CODES_OFF + r] = (float)bk; }
}

// ---------------- refine B: block per row, full fp32 scan (rare) ----------------
__global__ __launch_bounds__(256, 1)
void vq_refineB(const float* __restrict__ z, const float* __restrict__ emb,
                float* __restrict__ out) {
    __shared__ float zs[DIM];
    __shared__ float rv[8];
    __shared__ int   rix[8];
    const int tid = threadIdx.x, lane = tid & 31, wid = tid >> 5;
    const int cnt = g_fcnt2;
    for (int i = blockIdx.x; i < cnt; i += gridDim.x) {
        const int r = g_flist2[i];
        const int bb = r >> 10, hw = r & 1023;
        zs[tid] = __ldg(z + (size_t)bb * DIM * HW + (size_t)tid * HW + hw);
        __syncthreads();
        float bv = 3.4e38f; int bk = 0x7FFFFFFF;
        #pragma unroll
        for (int j = 0; j < 4; j++) {
            const int k = tid * 4 + j;
            const float4* ep = reinterpret_cast<const float4*>(emb + (size_t)k * DIM);
            float d = 0.f;
            #pragma unroll 8
            for (int q = 0; q < 64; q++) {
                float4 e = __ldg(ep + q);
                d += zs[4*q]*e.x + zs[4*q+1]*e.y + zs[4*q+2]*e.z + zs[4*q+3]*e.w;
            }
            float s = __ldg(g_en2 + k) - 2.f * d;
            if (s < bv || (s == bv && k < bk)) { bv = s; bk = k; }
        }
        #pragma unroll
        for (int o = 16; o; o >>= 1) {
            float ov = __shfl_xor_sync(0xFFFFFFFFu, bv, o);
            int   oi = __shfl_xor_sync(0xFFFFFFFFu, bk, o);
            if (ov < bv || (ov == bv && oi < bk)) { bv = ov; bk = oi; }
        }
        if (lane == 0) { rv[wid] = bv; rix[wid] = bk; }
        __syncthreads();
        if (tid == 0) {
            float v = rv[0]; int ix = rix[0];
            #pragma unroll
            for (int w = 1; w < 8; w++)
                if (rv[w] < v || (rv[w] == v && rix[w] < ix)) { v = rv[w]; ix = rix[w]; }
            g_codes[r] = ix;
            out[CODES_OFF + r] = (float)ix;
        }
        __syncthreads();
    }
}

// ---------------- gather z_q + loss ----------------
__global__ __launch_bounds__(256, 1)
void vq_gather(const float* __restrict__ z, const float* __restrict__ emb,
               float* __restrict__ out) {
    __shared__ float red[8];
    const int tid = threadIdx.x, wid = tid >> 5, lane = tid & 31;
    const int n0 = blockIdx.x * MT;
    const int b = n0 >> 10, hw0 = n0 & (HW - 1);
    const int nl = tid & 127, half = tid >> 7;
    const int code = __ldg(g_codes + n0 + nl);
    const float4* er = reinterpret_cast<const float4*>(emb + (size_t)code * DIM);
    float* zq = out + (size_t)b * DIM * HW + hw0 + nl;
    const float* zr = z + (size_t)b * DIM * HW + hw0 + nl;
    float lsum = 0.f;
    #pragma unroll 4
    for (int d4 = half; d4 < 64; d4 += 2) {
        float4 e = __ldg(er + d4);
        const int o0 = (d4 * 4) * HW;
        float z0 = zr[o0], z1 = zr[o0 + HW], z2 = zr[o0 + 2 * HW], z3 = zr[o0 + 3 * HW];
        zq[o0] = e.x; zq[o0 + HW] = e.y; zq[o0 + 2 * HW] = e.z; zq[o0 + 3 * HW] = e.w;
        float d0 = e.x - z0, d1 = e.y - z1, d2 = e.z - z2, d3 = e.w - z3;
        lsum = fmaf(d0, d0, lsum); lsum = fmaf(d1, d1, lsum);
        lsum = fmaf(d2, d2, lsum); lsum = fmaf(d3, d3, lsum);
    }
    #pragma unroll
    for (int o = 16; o; o >>= 1) lsum += __shfl_xor_sync(0xFFFFFFFFu, lsum, o);
    if (lane == 0) red[wid] = lsum;
    __syncthreads();
    if (tid == 0) {
        float s = 0.f;
        #pragma unroll
        for (int w = 0; w < 8; w++) s += red[w];
        g_partials[blockIdx.x] = s;
    }
}

// ---------------- finalize ----------------
__global__ void vq_fin(float* __restrict__ out) {
    if (threadIdx.x == 0 && blockIdx.x == 0) {
        float s = 0.f;
        for (int i = 0; i < GBLOCKS; i++) s += g_partials[i];
        out[LOSS_OFF] = 1.25f * s / (float)ZQ_ELEMS;
    }
}

extern "C" void kernel_launch(void* const* d_in, const int* in_sizes, int n_in,
                              void* d_out, int out_size) {
    const float* z   = (const float*)d_in[0];
    const float* emb = (const float*)d_in[1];
    if (n_in >= 2 && in_sizes[0] == KCODES * DIM) { const float* t = z; z = emb; emb = t; }
    float* out = (float*)d_out;

    cudaFuncSetAttribute(vq_gemm, cudaFuncAttributeMaxDynamicSharedMemorySize, SMEM_BYTES);
    vq_prep_e<<<(KCODES * 32 + 255) / 256, 256>>>(emb);
    vq_prep_z<<<dim3(32, 8, 32), dim3(32, 8)>>>(z);
    vq_gemm<<<GBLOCKS, 256, SMEM_BYTES>>>(out);
    vq_select<<<NTOT / 8, 256>>>(z, emb, out);
    vq_refineB<<<256, 256>>>(z, emb, out);
    vq_gather<<<GBLOCKS, 256>>>(z, emb, out);
    vq_fin<<<1, 32>>>(out);
}

// round 15
// speedup vs baseline: 1.3174x; 1.0297x over previous
#include <cuda_runtime.h>
#include <cuda_fp16.h>
#include <cstdint>

#define DIM    256
#define HW     1024
#define NTOT   32768
#define KCODES 1024
#define MT     128
#define GBLOCKS (NTOT / MT)              // 256
#define ZQ_ELEMS  ((size_t)NTOT * DIM)
#define CODES_OFF ZQ_ELEMS
#define LOSS_OFF  (ZQ_ELEMS + (size_t)NTOT)

// gemm smem layout (4B words)
#define OFF_A   0                         // 128 rows * 132 words (A hi only)
#define OFF_B   16896                     // 2 stages x 128*68
#define BSTG_W  8704
#define OFF_C   34304                     // 128*68 score tile (reused as RED post-loop)
#define OFF_ES  43008                     // 1024
#define OFF_ZNP 44032                     // 256
#define SMEM_WORDS 44288
#define SMEM_BYTES (SMEM_WORDS * 4)       // 177152

// empirically validated window constants (R8/R13/R14 exact codes)
#define C1W 5.2e-4f
#define C3W 0.06f

__device__ __half g_eh[(size_t)KCODES * DIM];
__device__ float  g_en2[KCODES];
__device__ int    g_en2imax;
__device__ int    g_codes[NTOT];
__device__ float  g_partials[GBLOCKS];
__device__ int    g_fcnt;                 // pair list
__device__ int    g_flist[NTOT];
__device__ int2   g_cand[NTOT];
__device__ int    g_fcnt2;                // overflow list
__device__ int    g_flist2[NTOT];

__device__ __forceinline__ uint32_t smem_u32(const void* p) {
    uint32_t a;
    asm("{ .reg .u64 t; cvta.to.shared.u64 t, %1; cvt.u32.u64 %0, t; }" : "=r"(a) : "l"(p));
    return a;
}
__device__ __forceinline__ uint32_t pack2h(float x0, float x1) {
    uint32_t h2;
    asm("cvt.rn.f16x2.f32 %0, %1, %2;" : "=r"(h2) : "f"(x1), "f"(x0));
    return h2;
}

#define MMA16(c, a, b0, b1)                                                   \
    asm volatile("mma.sync.aligned.m16n8k16.row.col.f32.f16.f16.f32 "         \
        "{%0,%1,%2,%3}, {%4,%5,%6,%7}, {%8,%9}, {%0,%1,%2,%3};"               \
        : "+f"((c)[0]), "+f"((c)[1]), "+f"((c)[2]), "+f"((c)[3])              \
        : "r"((a)[0]), "r"((a)[1]), "r"((a)[2]), "r"((a)[3]),                 \
          "r"(b0), "r"(b1))
#define LDSM4(r0, r1, r2, r3, addr)                                           \
    asm volatile("ldmatrix.sync.aligned.m8n8.x4.shared.b16 {%0,%1,%2,%3}, [%4];" \
        : "=r"(r0), "=r"(r1), "=r"(r2), "=r"(r3) : "r"(addr))
#define CPA16(dst, src) \
    asm volatile("cp.async.cg.shared.global [%0], [%1], 16;" :: "r"(dst), "l"(src) : "memory")
#define CP_COMMIT() asm volatile("cp.async.commit_group;" ::: "memory")
#define CP_WAIT1()  asm volatile("cp.async.wait_group 1;" ::: "memory")

#define MRG(v, ix, M1, I1, M2, I2, M3)                                         \
    if ((v) < (M1) || ((v) == (M1) && (ix) < (I1))) { (M3)=(M2); (M2)=(M1); (I2)=(I1); (M1)=(v); (I1)=(ix); } \
    else if ((v) < (M2) || ((v) == (M2) && (ix) < (I2))) { (M3)=(M2); (M2)=(v); (I2)=(ix); } \
    else if ((v) < (M3)) { (M3)=(v); }

// ---------------- prepass: emb hi-split + ||e||^2 + counters ----------------
__global__ void vq_prep_e(const float* __restrict__ emb) {
    if (blockIdx.x == 0 && threadIdx.x == 0) { g_fcnt = 0; g_fcnt2 = 0; }
    int gw = (blockIdx.x * blockDim.x + threadIdx.x) >> 5, lane = threadIdx.x & 31;
    if (gw >= KCODES) return;
    const float* row = emb + (size_t)gw * DIM;
    const int d0 = lane * 8;
    float4 v0 = *reinterpret_cast<const float4*>(row + d0);
    float4 v1 = *reinterpret_cast<const float4*>(row + d0 + 4);
    uint4 h;
    h.x = pack2h(v0.x, v0.y);
    h.y = pack2h(v0.z, v0.w);
    h.z = pack2h(v1.x, v1.y);
    h.w = pack2h(v1.z, v1.w);
    *reinterpret_cast<uint4*>(g_eh + (size_t)gw * DIM + d0) = h;
    float s = v0.x*v0.x + v0.y*v0.y + v0.z*v0.z + v0.w*v0.w
            + v1.x*v1.x + v1.y*v1.y + v1.z*v1.z + v1.w*v1.w;
    #pragma unroll
    for (int o = 16; o; o >>= 1) s += __shfl_xor_sync(0xFFFFFFFFu, s, o);
    if (lane == 0) {
        g_en2[gw] = s;
        atomicMax(&g_en2imax, __float_as_int(s));
    }
}

// B chunk loader
__device__ __forceinline__ void b_cpa(int c, uint32_t dstB, int tid) {
    const int nc = c >> 1, kh = c & 1;
    const __half* src = g_eh + (size_t)(nc * 128) * DIM + kh * 128;
    #pragma unroll
    for (int q = 0; q < 8; q++) {
        int idx = tid + q * 256;
        int n = idx >> 4, j = idx & 15;
        CPA16(dstB + n * 272 + j * 16, src + (size_t)n * DIM + j * 8);
    }
}

// ---------------- fused gemm + in-smem top-3 scan + decision ----------------
__global__ __launch_bounds__(256, 1)
void vq_gemm(const float* __restrict__ z, float* __restrict__ out) {
    extern __shared__ __align__(16) uint32_t sw[];
    float* es = reinterpret_cast<float*>(sw + OFF_ES);
    const int tid = threadIdx.x, wid = tid >> 5, lane = tid & 31;
    const int wm = wid & 3, wn = wid >> 2;
    const int tig = lane & 3, grp = lane >> 2;
    const int n0 = blockIdx.x * MT;
    const int b = n0 >> 10, hw0 = n0 & (HW - 1);

    const uint32_t sbase = smem_u32(sw);
    const uint32_t bBase = sbase + OFF_B * 4;

    // start B prefetch first
    b_cpa(0, bBase, tid);
    CP_COMMIT();
    b_cpa(1, bBase + BSTG_W * 4, tid);
    CP_COMMIT();

    // A: direct load from z, hi-split into smem; row-norm partial for free
    {
        const int m = tid & 127, khalf = tid >> 7;
        const float* zc = z + (size_t)b * DIM * HW + hw0 + m;
        uint32_t* ah = sw + OFF_A + m * 132 + khalf * 64;
        float zn = 0.f;
        #pragma unroll 8
        for (int j = 0; j < 64; j++) {
            const int k = khalf * 128 + 2 * j;
            float x0 = __ldg(zc + (size_t)k * HW);
            float x1 = __ldg(zc + (size_t)(k + 1) * HW);
            zn = fmaf(x0, x0, fmaf(x1, x1, zn));
            ah[j] = pack2h(x0, x1);
        }
        reinterpret_cast<float*>(sw + OFF_ZNP)[tid] = zn;
    }
    for (int i = tid; i < KCODES; i += 256) es[i] = g_en2[i];

    const int mrow = wm * 32 + ((lane >> 3) & 1) * 8 + (lane & 7);
    const uint32_t aAddr = sbase + mrow * 528 + (lane >> 4) * 16;
    const int nrow = wn * 64 + ((lane >> 4) << 3) + (lane & 7);
    const uint32_t bAddr0 = bBase + nrow * 272 + ((lane >> 3) & 1) * 16;

    // per-thread running top-3 for its owned row
    const int srow = tid & 127, shf = tid >> 7;
    float M1 = 3.4e38f, M2 = 3.4e38f, M3 = 3.4e38f;
    int I1 = 0, I2 = 0;
    __half Th = __ushort_as_half((unsigned short)0x7C00u);   // +inf

    float acc[2][8][4];

    #pragma unroll 1
    for (int c = 0; c < 16; c++) {
        const int nc = c >> 1, st = c & 1;
        CP_WAIT1();
        __syncthreads();

        if ((c & 1) == 0) {
            #pragma unroll
            for (int mt = 0; mt < 2; mt++)
                #pragma unroll
                for (int nt = 0; nt < 8; nt++)
                    #pragma unroll
                    for (int q = 0; q < 4; q++) acc[mt][nt][q] = 0.f;
        }

        #pragma unroll
        for (int kk = 0; kk < 8; kk++) {
            const uint32_t ak = (c & 1) * 256 + kk * 32;
            uint32_t ah[2][4];
            #pragma unroll
            for (int mt = 0; mt < 2; mt++)
                LDSM4(ah[mt][0], ah[mt][1], ah[mt][2], ah[mt][3],
                      aAddr + mt * (16 * 528) + ak);
            const uint32_t bk = st * (BSTG_W * 4) + kk * 32;
            #pragma unroll
            for (int ntp = 0; ntp < 4; ntp++) {
                uint32_t bh[4];
                LDSM4(bh[0], bh[1], bh[2], bh[3], bAddr0 + bk + ntp * (16 * 272));
                #pragma unroll
                for (int hf = 0; hf < 2; hf++) {
                    const int nt = ntp * 2 + hf;
                    #pragma unroll
                    for (int mt = 0; mt < 2; mt++)
                        MMA16(acc[mt][nt], ah[mt], bh[hf * 2], bh[hf * 2 + 1]);
                }
            }
        }
        __syncthreads();

        if (c + 2 < 16) { b_cpa(c + 2, bBase + st * (BSTG_W * 4), tid); CP_COMMIT(); }

        if (c & 1) {
            // stage scores into C smem tile
            #pragma unroll
            for (int mt = 0; mt < 2; mt++) {
                const int rbase = wm * 32 + mt * 16 + grp;
                #pragma unroll
                for (int nt = 0; nt < 8; nt++) {
                    const int col = wn * 64 + nt * 8 + tig * 2;
                    const float e0 = es[nc * 128 + col], e1 = es[nc * 128 + col + 1];
                    const int cw = wn * 32 + nt * 4 + tig;
                    __half2 p01 = __floats2half2_rn(fmaf(-2.f, acc[mt][nt][0], e0),
                                                    fmaf(-2.f, acc[mt][nt][1], e1));
                    __half2 p23 = __floats2half2_rn(fmaf(-2.f, acc[mt][nt][2], e0),
                                                    fmaf(-2.f, acc[mt][nt][3], e1));
                    sw[OFF_C + rbase * 68 + cw]       = *reinterpret_cast<uint32_t*>(&p01);
                    sw[OFF_C + (rbase + 8) * 68 + cw] = *reinterpret_cast<uint32_t*>(&p23);
                }
            }
            __syncthreads();
            // pack-pruned top-3 scan of owned row half (ascending k)
            const uint32_t* crow = sw + OFF_C + srow * 68 + shf * 32;
            const int kb0 = nc * 128 + shf * 64;
            #pragma unroll
            for (int p = 0; p < 8; p++) {
                uint4 v = *reinterpret_cast<const uint4*>(crow + p * 4);
                const __half2* hh = reinterpret_cast<const __half2*>(&v);
                __half2 mm = __hmin2(__hmin2(hh[0], hh[1]), __hmin2(hh[2], hh[3]));
                __half pm = __hmin(__low2half(mm), __high2half(mm));
                if (__hlt(pm, Th)) {
                    const int k0 = kb0 + p * 8;
                    #pragma unroll
                    for (int t = 0; t < 4; t++) {
                        float2 s2 = __half22float2(hh[t]);
                        const int kk2 = k0 + t * 2;
                        if (s2.x < M3) {
                            if (s2.x < M1)      { M3 = M2; M2 = M1; I2 = I1; M1 = s2.x; I1 = kk2; }
                            else if (s2.x < M2) { M3 = M2; M2 = s2.x; I2 = kk2; }
                            else                { M3 = s2.x; }
                        }
                        if (s2.y < M3) {
                            if (s2.y < M1)      { M3 = M2; M2 = M1; I2 = I1; M1 = s2.y; I1 = kk2 + 1; }
                            else if (s2.y < M2) { M3 = M2; M2 = s2.y; I2 = kk2 + 1; }
                            else                { M3 = s2.y; }
                        }
                    }
                    Th = __float2half_ru(M3);
                }
            }
        }
    }

    // merge the two half-threads per row, decide
    __syncthreads();
    float* RED = reinterpret_cast<float*>(sw + OFF_C);
    int*   REDi = reinterpret_cast<int*>(sw + OFF_C);
    RED[tid * 5] = M1; REDi[tid * 5 + 1] = I1;
    RED[tid * 5 + 2] = M2; REDi[tid * 5 + 3] = I2;
    RED[tid * 5 + 4] = M3;
    __syncthreads();

    if (tid < 128) {
        const int e1 = (128 + tid) * 5;
        MRG(RED[e1], REDi[e1 + 1], M1, I1, M2, I2, M3)
        MRG(RED[e1 + 2], REDi[e1 + 3], M1, I1, M2, I2, M3)
        M3 = fminf(M3, RED[e1 + 4]);

        const int r = n0 + tid;
        g_codes[r] = I1;
        out[CODES_OFF + r] = (float)I1;

        const float* znp = reinterpret_cast<const float*>(sw + OFF_ZNP);
        const float czn = C1W * (znp[tid] + znp[tid + 128]);
        const float w1 = fmaf(C1W, __ldg(g_en2 + I1), C3W) + czn;
        const float wmax = fmaf(C1W, __int_as_float(g_en2imax), C3W) + czn;
        if (M3 - wmax <= M1 + w1) {
            int slot = atomicAdd(&g_fcnt2, 1);
            g_flist2[slot] = r;
        } else {
            const float w2 = fmaf(C1W, __ldg(g_en2 + I2), C3W) + czn;
            if (M2 - w2 <= M1 + w1) {
                int slot = atomicAdd(&g_fcnt, 1);
                g_flist[slot] = r;
                g_cand[r] = make_int2(I1, I2);
            }
        }
    }
}

// ---------------- refine A: warp per row, 2 exact fp32 dots ----------------
__global__ __launch_bounds__(256, 1)
void vq_refineA(const float* __restrict__ z, const float* __restrict__ emb,
                float* __restrict__ out) {
    const int tid = threadIdx.x, lane = tid & 31, wq = tid >> 5;
    const int gw = blockIdx.x * 8 + wq;
    const int nwarp = gridDim.x * 8;
    const int cnt = g_fcnt;
    for (int i = gw; i < cnt; i += nwarp) {
        const int r = g_flist[i];
        const int2 cd = g_cand[r];
        const int bb = r >> 10, hw = r & 1023;
        const float* zr = z + (size_t)bb * DIM * HW + hw;
        float zo[8];
        #pragma unroll
        for (int t = 0; t < 8; t++) zo[t] = __ldg(zr + (size_t)(lane * 8 + t) * HW);
        float bv = 3.4e38f; int bk = 0x7FFFFFFF;
        const int ks[2] = {cd.x, cd.y};
        #pragma unroll
        for (int c = 0; c < 2; c++) {
            const int k = ks[c];
            const float4* ep = reinterpret_cast<const float4*>(emb + (size_t)k * DIM + lane * 8);
            float4 ea = __ldg(ep), eb = __ldg(ep + 1);
            float d = zo[0]*ea.x + zo[1]*ea.y + zo[2]*ea.z + zo[3]*ea.w
                    + zo[4]*eb.x + zo[5]*eb.y + zo[6]*eb.z + zo[7]*eb.w;
            #pragma unroll
            for (int o = 16; o; o >>= 1) d += __shfl_xor_sync(0xFFFFFFFFu, d, o);
            float s = __ldg(g_en2 + k) - 2.f * d;
            if (s < bv || (s == bv && k < bk)) { bv = s; bk = k; }
        }
        if (lane == 0) { g_codes[r] = bk; out[CODES_OFF + r] = (float)bk; }
    }
}

// ---------------- refine B: block per row, full fp32 scan (rare) ----------------
__global__ __launch_bounds__(256, 1)
void vq_refineB(const float* __restrict__ z, const float* __restrict__ emb,
                float* __restrict__ out) {
    __shared__ float zs[DIM];
    __shared__ float rv[8];
    __shared__ int   rix[8];
    const int tid = threadIdx.x, lane = tid & 31, wid = tid >> 5;
    const int cnt = g_fcnt2;
    for (int i = blockIdx.x; i < cnt; i += gridDim.x) {
        const int r = g_flist2[i];
        const int bb = r >> 10, hw = r & 1023;
        zs[tid] = __ldg(z + (size_t)bb * DIM * HW + (size_t)tid * HW + hw);
        __syncthreads();
        float bv = 3.4e38f; int bk = 0x7FFFFFFF;
        #pragma unroll
        for (int j = 0; j < 4; j++) {
            const int k = tid * 4 + j;
            const float4* ep = reinterpret_cast<const float4*>(emb + (size_t)k * DIM);
            float d = 0.f;
            #pragma unroll 8
            for (int q = 0; q < 64; q++) {
                float4 e = __ldg(ep + q);
                d += zs[4*q]*e.x + zs[4*q+1]*e.y + zs[4*q+2]*e.z + zs[4*q+3]*e.w;
            }
            float s = __ldg(g_en2 + k) - 2.f * d;
            if (s < bv || (s == bv && k < bk)) { bv = s; bk = k; }
        }
        #pragma unroll
        for (int o = 16; o; o >>= 1) {
            float ov = __shfl_xor_sync(0xFFFFFFFFu, bv, o);
            int   oi = __shfl_xor_sync(0xFFFFFFFFu, bk, o);
            if (ov < bv || (ov == bv && oi < bk)) { bv = ov; bk = oi; }
        }
        if (lane == 0) { rv[wid] = bv; rix[wid] = bk; }
        __syncthreads();
        if (tid == 0) {
            float v = rv[0]; int ix = rix[0];
            #pragma unroll
            for (int w = 1; w < 8; w++)
                if (rv[w] < v || (rv[w] == v && rix[w] < ix)) { v = rv[w]; ix = rix[w]; }
            g_codes[r] = ix;
            out[CODES_OFF + r] = (float)ix;
        }
        __syncthreads();
    }
}

// ---------------- gather z_q + loss ----------------
__global__ __launch_bounds__(256, 1)
void vq_gather(const float* __restrict__ z, const float* __restrict__ emb,
               float* __restrict__ out) {
    __shared__ float red[8];
    const int tid = threadIdx.x, wid = tid >> 5, lane = tid & 31;
    const int n0 = blockIdx.x * MT;
    const int b = n0 >> 10, hw0 = n0 & (HW - 1);
    const int nl = tid & 127, half = tid >> 7;
    const int code = __ldg(g_codes + n0 + nl);
    const float4* er = reinterpret_cast<const float4*>(emb + (size_t)code * DIM);
    float* zq = out + (size_t)b * DIM * HW + hw0 + nl;
    const float* zr = z + (size_t)b * DIM * HW + hw0 + nl;
    float lsum = 0.f;
    #pragma unroll 4
    for (int d4 = half; d4 < 64; d4 += 2) {
        float4 e = __ldg(er + d4);
        const int o0 = (d4 * 4) * HW;
        float z0 = zr[o0], z1 = zr[o0 + HW], z2 = zr[o0 + 2 * HW], z3 = zr[o0 + 3 * HW];
        zq[o0] = e.x; zq[o0 + HW] = e.y; zq[o0 + 2 * HW] = e.z; zq[o0 + 3 * HW] = e.w;
        float d0 = e.x - z0, d1 = e.y - z1, d2 = e.z - z2, d3 = e.w - z3;
        lsum = fmaf(d0, d0, lsum); lsum = fmaf(d1, d1, lsum);
        lsum = fmaf(d2, d2, lsum); lsum = fmaf(d3, d3, lsum);
    }
    #pragma unroll
    for (int o = 16; o; o >>= 1) lsum += __shfl_xor_sync(0xFFFFFFFFu, lsum, o);
    if (lane == 0) red[wid] = lsum;
    __syncthreads();
    if (tid == 0) {
        float s = 0.f;
        #pragma unroll
        for (int w = 0; w < 8; w++) s += red[w];
        g_partials[blockIdx.x] = s;
    }
}

// ---------------- finalize ----------------
__global__ void vq_fin(float* __restrict__ out) {
    if (threadIdx.x == 0 && blockIdx.x == 0) {
        float s = 0.f;
        for (int i = 0; i < GBLOCKS; i++) s += g_partials[i];
        out[LOSS_OFF] = 1.25f * s / (float)ZQ_ELEMS;
    }
}

extern "C" void kernel_launch(void* const* d_in, const int* in_sizes, int n_in,
                              void* d_out, int out_size) {
    const float* z   = (const float*)d_in[0];
    const float* emb = (const float*)d_in[1];
    if (n_in >= 2 && in_sizes[0] == KCODES * DIM) { const float* t = z; z = emb; emb = t; }
    float* out = (float*)d_out;

    cudaFuncSetAttribute(vq_gemm, cudaFuncAttributeMaxDynamicSharedMemorySize, SMEM_BYTES);
    vq_prep_e<<<(KCODES * 32 + 255) / 256, 256>>>(emb);
    vq_gemm<<<GBLOCKS, 256, SMEM_BYTES>>>(z, out);
    vq_refineA<<<128, 256>>>(z, emb, out);
    vq_refineB<<<256, 256>>>(z, emb, out);
    vq_gather<<<GBLOCKS, 256>>>(z, emb, out);
    vq_fin<<<1, 32>>>(out);
}